// round 16
// baseline (speedup 1.0000x reference)
#include <cuda_runtime.h>
#include <stdint.h>

// ---------------------------------------------------------------------------
// LJ edge-message passing:  out[n] = sum_{e: dst[e]=n} f(|dr_e|) * unit(dr_e)
//                                    - 0.1 * v[n]
// dr_e = x[dst[e]] - x[src[e]]
// f(r) = 4 * s^6 * (12 s^6 - 6) / rc,  rc = max(r, 0.1), s = 1/rc
// ---------------------------------------------------------------------------

#define NMAX 100352          // >= 100000 nodes, padded
#define GAMMA 0.1f

// Device-global scratch (no allocations allowed in kernel_launch).
__device__ float4 g_xpad[NMAX];   // x padded to float4 for 1-sector gathers
__device__ float4 g_acc[NMAX];    // accumulator, float4 for red.v4
__device__ int    g_is64;         // index dtype flag (1 = int64, 0 = int32)

// --- dtype sniffer: deterministic, reads a few leading entries -------------
__global__ void sniff_kernel(const void* __restrict__ src, int n_edges, int n_nodes) {
    if (blockIdx.x == 0 && threadIdx.x == 0) {
        const long long* p = (const long long*)src;
        int k = 64;
        if (2 * k > n_edges) k = n_edges / 2;
        int ok = 1;
        for (int i = 0; i < k; i++) {
            long long val = p[i];
            if (val < 0 || val >= (long long)n_nodes) { ok = 0; break; }
        }
        g_is64 = ok;
    }
}

// --- prep: pad x rows to float4, zero accumulator ---------------------------
__global__ void prep_kernel(const float* __restrict__ x, int n) {
    int i = blockIdx.x * blockDim.x + threadIdx.x;
    if (i < n) {
        float4 xp;
        xp.x = x[3 * i + 0];
        xp.y = x[3 * i + 1];
        xp.z = x[3 * i + 2];
        xp.w = 0.0f;
        g_xpad[i] = xp;
        g_acc[i]  = make_float4(0.0f, 0.0f, 0.0f, 0.0f);
    }
}

// --- per-edge force + vector-atomic scatter ---------------------------------
__global__ void __launch_bounds__(256) edge_kernel(
    const void* __restrict__ src_raw,
    const void* __restrict__ dst_raw,
    int n_edges)
{
    int e = blockIdx.x * blockDim.x + threadIdx.x;
    if (e >= n_edges) return;

    int s, d;
    if (g_is64) {
        s = (int)((const long long*)src_raw)[e];
        d = (int)((const long long*)dst_raw)[e];
    } else {
        s = ((const int*)src_raw)[e];
        d = ((const int*)dst_raw)[e];
    }

    float4 xs = __ldg(&g_xpad[s]);
    float4 xd = __ldg(&g_xpad[d]);

    float dx = xd.x - xs.x;
    float dy = xd.y - xs.y;
    float dz = xd.z - xs.z;

    float r2 = dx * dx + dy * dy + dz * dz;
    float r  = sqrtf(r2);

    float rc = fmaxf(r, 0.1f);           // MIN_R clamp
    float si = 1.0f / rc;                // s = RC/rc, RC=1
    float s2 = si * si;
    float s6 = s2 * s2 * s2;
    float f  = 4.0f * s6 * (12.0f * s6 - 6.0f) * si;   // lj_force(rc)

    float coef = f / fmaxf(r, 1e-12f);   // f * unit_dr uses unclamped r

    float mx = coef * dx;
    float my = coef * dy;
    float mz = coef * dz;

    // One 16B vector reduction instead of three scalar atomics.
    asm volatile(
        "red.global.add.v4.f32 [%0], {%1, %2, %3, %4};"
        :: "l"(&g_acc[d]), "f"(mx), "f"(my), "f"(mz), "f"(0.0f)
        : "memory");
}

// --- finalize: out = acc - gamma * v ----------------------------------------
__global__ void finalize_kernel(const float* __restrict__ v,
                                float* __restrict__ out, int n) {
    int i = blockIdx.x * blockDim.x + threadIdx.x;
    if (i < n) {
        float4 a = g_acc[i];
        out[3 * i + 0] = a.x - GAMMA * v[3 * i + 0];
        out[3 * i + 1] = a.y - GAMMA * v[3 * i + 1];
        out[3 * i + 2] = a.z - GAMMA * v[3 * i + 2];
    }
}

extern "C" void kernel_launch(void* const* d_in, const int* in_sizes, int n_in,
                              void* d_out, int out_size) {
    const float* x   = (const float*)d_in[0];
    const float* v   = (const float*)d_in[1];
    const void*  src = d_in[2];
    const void*  dst = d_in[3];

    int n_nodes = in_sizes[0] / 3;
    int n_edges = in_sizes[2];
    if (n_nodes > NMAX) n_nodes = NMAX;   // safety (problem is fixed at 100k)

    const int TB = 256;
    int node_blocks = (n_nodes + TB - 1) / TB;
    int edge_blocks = (n_edges + TB - 1) / TB;

    sniff_kernel<<<1, 32>>>(src, n_edges, n_nodes);
    prep_kernel<<<node_blocks, TB>>>(x, n_nodes);
    edge_kernel<<<edge_blocks, TB>>>(src, dst, n_edges);
    finalize_kernel<<<node_blocks, TB>>>(v, d_out ? (float*)d_out : nullptr, n_nodes);
}